// round 6
// baseline (speedup 1.0000x reference)
#include <cuda_runtime.h>
#include <cuda_bf16.h>

// DiscriminativeLoss, two kernels.
//   data  : [D=32][N=524288] float32 (dim-major), labels: [N] int32 in [0,16)
//
// K1 (k_sums): per 128-point tile, front-batched LDG.128 -> STS.128 stage,
// counting-sort indices by label (1 shared atomic/point), thread (k, dr)
// walks list k for dims dr, dr+16. ~4.6 TB/s measured.
// K2 (k_var): SINGLE WAVE, even load: 2048 blocks x 128 thr, 2 pts/thread,
// all blocks co-resident (launch_bounds(128,14) -> <=36 regs, 14 blk/SM).
// R5 showed this access pattern runs ~5.9 TB/s-equivalent but lost 2x to a
// straggler wave (1024 blocks vs 888 resident). 8 chunks of 4 front-batched
// LDG.64s. Centers in smem [d][k] (conflict-free). Last block adds dist+reg,
// writes out[0], resets globals (graph-replay invariant).

#define DD 32
#define KK 16
#define TILE 128
#define XSTR 132   // 128+4: float4-aligned stores, banks spread by 4d+idx

__device__ float g_sums[KK * DD];   // [k][d]
__device__ float g_counts[KK];
__device__ float g_var;
__device__ unsigned int g_done;

__global__ __launch_bounds__(256, 6)
void k_sums(const float* __restrict__ data, const int* __restrict__ labels, int npts) {
    __shared__ float s_x[DD * XSTR];            // 16.9 KB
    __shared__ unsigned char s_list[KK][TILE];  // 2 KB
    __shared__ int s_cnt[KK];

    const int t  = threadIdx.x;
    const int k  = t >> 4;    // cluster this thread owns
    const int dr = t & 15;    // dims dr and dr+16

    float acc0 = 0.f, acc1 = 0.f;
    int ccnt = 0;

    const int ntiles = npts / TILE;             // 4096
    for (int tile = blockIdx.x; tile < ntiles; tile += gridDim.x) {
        const int n0 = tile * TILE;
        __syncthreads();                        // prev phase-B readers done
        if (t < KK) s_cnt[t] = 0;

        // Front-batched loads: 4 independent LDG.128 before any store
        float4 v[4];
        #pragma unroll
        for (int j = 0; j < 4; j++) {
            int idx = t + j * 256;              // 0..1023
            v[j] = *reinterpret_cast<const float4*>(
                data + (size_t)(idx >> 5) * npts + n0 + ((idx & 31) << 2));
        }
        int lab = (t < TILE) ? labels[n0 + t] : 0;
        #pragma unroll
        for (int j = 0; j < 4; j++) {
            int idx = t + j * 256;
            *reinterpret_cast<float4*>(
                s_x + (idx >> 5) * XSTR + ((idx & 31) << 2)) = v[j];
        }
        __syncthreads();                        // s_cnt zeroed, s_x filled

        if (t < TILE) {
            int pos = atomicAdd(&s_cnt[lab], 1);
            s_list[lab][pos] = (unsigned char)t;
        }
        __syncthreads();                        // lists ready

        const int cnt = s_cnt[k];
        const float* r0 = s_x + dr * XSTR;
        const float* r1 = s_x + (dr + 16) * XSTR;
        const unsigned char* lst = s_list[k];
        for (int i = 0; i < cnt; i++) {
            int idx = lst[i];
            acc0 += r0[idx];
            acc1 += r1[idx];
        }
        if (dr == 0) ccnt += cnt;
    }
    atomicAdd(&g_sums[k * DD + dr], acc0);
    atomicAdd(&g_sums[k * DD + dr + 16], acc1);
    if (dr == 0) atomicAdd(&g_counts[k], (float)ccnt);
}

__global__ __launch_bounds__(128, 14)
void k_var(const float* __restrict__ data, const int* __restrict__ labels,
           int npts, float* __restrict__ out) {
    __shared__ float s_c[DD * KK];   // [d][k]: conflict-free label lookups
    __shared__ float s_red[4];
    __shared__ float s_reg[KK];
    __shared__ unsigned int s_rank;
    const int t = threadIdx.x;

    // Every block derives centers (512 divides, trivial)
    #pragma unroll
    for (int j = t; j < DD * KK; j += 128) {
        int d = j >> 4, kk = j & 15;
        s_c[j] = g_sums[kk * DD + d] / g_counts[kk];
    }
    __syncthreads();

    // One pair of points per thread; 2048-block grid covers N exactly,
    // all blocks co-resident -> single wave, no straggler.
    const int n = (blockIdx.x * 128 + t) * 2;
    const int2 lab = *reinterpret_cast<const int2*>(labels + n);
    float a0 = 0.f, a1 = 0.f;

    #pragma unroll
    for (int c = 0; c < 8; c++) {
        // Loads-only: 4 independent LDG.64s issued before any use
        float2 v[4];
        #pragma unroll
        for (int j = 0; j < 4; j++)
            v[j] = *reinterpret_cast<const float2*>(
                data + (size_t)(c * 4 + j) * npts + n);
        #pragma unroll
        for (int j = 0; j < 4; j++) {
            const float* cr = s_c + (c * 4 + j) * KK;
            float d0 = cr[lab.x] - v[j].x; a0 = fmaf(d0, d0, a0);
            float d1 = cr[lab.y] - v[j].y; a1 = fmaf(d1, d1, a1);
        }
    }
    float h0 = fmaxf(sqrtf(a0) - 0.5f, 0.f);
    float h1 = fmaxf(sqrtf(a1) - 0.5f, 0.f);
    float vsum = h0 * h0 + h1 * h1;

    #pragma unroll
    for (int off = 16; off > 0; off >>= 1)
        vsum += __shfl_down_sync(0xffffffffu, vsum, off);
    if ((t & 31) == 0) s_red[t >> 5] = vsum;
    __syncthreads();
    if (t == 0) {
        float tot = s_red[0] + s_red[1] + s_red[2] + s_red[3];
        atomicAdd(&g_var, tot);
        __threadfence();
        s_rank = atomicAdd(&g_done, 1u);
    }
    __syncthreads();

    // Last block: dist + reg terms, final write, re-zero for replay
    if (s_rank == gridDim.x - 1) {
        __threadfence();
        __syncthreads();                 // make s_red reusable
        if (t < KK) {
            float s = 0.f;
            #pragma unroll
            for (int d = 0; d < DD; d++) { float c = s_c[d * KK + t]; s += c * c; }
            s_reg[t] = sqrtf(s);
        }
        // distance term: 256 ordered pairs over 128 threads (2 each)
        float dsum = 0.f;
        #pragma unroll
        for (int p = 0; p < 2; p++) {
            const int pair = t + p * 128;
            const int i = pair >> 4, j = pair & 15;
            if (i != j) {
                float sq = 0.f;
                #pragma unroll
                for (int d = 0; d < DD; d++) {
                    float df = s_c[d * KK + i] - s_c[d * KK + j];
                    sq += df * df;
                }
                float h = fmaxf(3.0f - sqrtf(sq), 0.f);   // 2*DELTA_DIST
                dsum += h * h;
            }
        }
        #pragma unroll
        for (int off = 16; off > 0; off >>= 1)
            dsum += __shfl_down_sync(0xffffffffu, dsum, off);
        if ((t & 31) == 0) s_red[t >> 5] = dsum;
        __syncthreads();
        if (t == 0) {
            float dtot = s_red[0] + s_red[1] + s_red[2] + s_red[3];
            float reg = 0.f;
            #pragma unroll
            for (int kk = 0; kk < KK; kk++) reg += s_reg[kk];
            out[0] = g_var * (1.0f / KK)
                   + dtot * (1.0f / (KK * (KK - 1)))
                   + 0.001f * reg * (1.0f / KK);
            g_var = 0.f;
            g_done = 0u;
        }
        for (int jz = t; jz < KK * DD; jz += 128) g_sums[jz] = 0.f;
        if (t < KK) g_counts[t] = 0.f;
    }
}

extern "C" void kernel_launch(void* const* d_in, const int* in_sizes, int n_in,
                              void* d_out, int out_size) {
    const float* data   = (const float*)d_in[0];
    const int*   labels = (const int*)d_in[1];
    const int    npts   = in_sizes[1];          // 512*1024
    float* out = (float*)d_out;

    k_sums<<<888, 256>>>(data, labels, npts);   // 6 blocks/SM, single wave
    const int vblocks = npts / (128 * 2);       // 2048, exact, all co-resident
    k_var<<<vblocks, 128>>>(data, labels, npts, out);
}